// round 12
// baseline (speedup 1.0000x reference)
#include <cuda_runtime.h>
#include <cstdint>

#define B_  64
#define N_  256
#define H_  1024
#define NK_ 768     // N*K, K=3

// Device-global scratch (sanctioned no-allocation workaround).
// g_weight layout: [b][kk][n][m-PERMUTED]  (3 tap-planes of 256x256 per batch).
// g_f / g_wl: k-dimension permuted within each aligned 8-group as
// 0,4,1,5,2,6,3,7 so the MMA fragment pair (k=tig, k=tig+4) is word-adjacent
// -> LDS.64 fragment loads. All stored as tf32 bit patterns (cvt.rna once;
// identical numerics to converting at every read).
__device__ uint32_t g_weight[(size_t)B_ * 3 * N_ * N_];   // 48 MB
__device__ uint32_t g_f [(size_t)B_ * N_ * H_];           // f, k-perm, tf32 bits
__device__ uint32_t g_k [(size_t)B_ * N_ * H_];           // k, UNpermuted tf32 bits
__device__ uint32_t g_wl[(size_t)NK_ * H_];               // W_lin, k-perm, tf32 bits

__device__ __forceinline__ uint32_t f2tf(float x) {
    uint32_t r;
    asm("cvt.rna.tf32.f32 %0, %1;" : "=r"(r) : "f"(x));
    return r;
}

__device__ __forceinline__ void mma8(float* c, const uint32_t* a, const uint32_t* b) {
    asm volatile(
        "mma.sync.aligned.m16n8k8.row.col.f32.tf32.tf32.f32 "
        "{%0,%1,%2,%3}, {%4,%5,%6,%7}, {%8,%9}, {%0,%1,%2,%3};\n"
        : "+f"(c[0]), "+f"(c[1]), "+f"(c[2]), "+f"(c[3])
        : "r"(a[0]), "r"(a[1]), "r"(a[2]), "r"(a[3]), "r"(b[0]), "r"(b[1]));
}

__device__ __forceinline__ void cpa16(uint32_t dst, const void* src) {
    asm volatile("cp.async.cg.shared.global [%0], [%1], 16;\n"
                 :: "r"(dst), "l"(src) : "memory");
}
__device__ __forceinline__ void cpa16z(uint32_t dst, const void* src, int srcsz) {
    asm volatile("cp.async.cg.shared.global [%0], [%1], 16, %2;\n"
                 :: "r"(dst), "l"(src), "r"(srcsz) : "memory");
}
#define CP_COMMIT() asm volatile("cp.async.commit_group;\n" ::: "memory")
#define CP_WAIT1()  asm volatile("cp.async.wait_group 1;\n" ::: "memory")
#define CP_WAIT0()  asm volatile("cp.async.wait_group 0;\n" ::: "memory")

// ---------------------------------------------------------------------------
// Pre-pass A: fp32 -> tf32 bits, k-PAIR-PERMUTED within each aligned 8-group:
// out[0..7] = in[0],in[4],in[1],in[5],in[2],in[6],in[3],in[7].
// ---------------------------------------------------------------------------
__global__ void cvt_perm_kernel(const float* __restrict__ src,
                                uint32_t* __restrict__ dst, int n8) {
    int i = blockIdx.x * blockDim.x + threadIdx.x;
    int stride = gridDim.x * blockDim.x;
    for (; i < n8; i += stride) {
        float4 a = ((const float4*)src)[2 * i];
        float4 b = ((const float4*)src)[2 * i + 1];
        uint4 o0, o1;
        o0.x = f2tf(a.x); o0.y = f2tf(b.x); o0.z = f2tf(a.y); o0.w = f2tf(b.y);
        o1.x = f2tf(a.z); o1.y = f2tf(b.z); o1.z = f2tf(a.w); o1.w = f2tf(b.w);
        ((uint4*)dst)[2 * i]     = o0;
        ((uint4*)dst)[2 * i + 1] = o1;
    }
}

// Pre-pass B: plain fp32 -> tf32 bits (for g_k; gemm2's B is not permuted).
__global__ void cvt_kernel(const float* __restrict__ src,
                           uint32_t* __restrict__ dst, int n4) {
    int i = blockIdx.x * blockDim.x + threadIdx.x;
    int stride = gridDim.x * blockDim.x;
    for (; i < n4; i += stride) {
        float4 v = ((const float4*)src)[i];
        uint4 o;
        o.x = f2tf(v.x); o.y = f2tf(v.y); o.z = f2tf(v.z); o.w = f2tf(v.w);
        ((uint4*)dst)[i] = o;
    }
}

// ---------------------------------------------------------------------------
// GEMM1: weight[(b,n)][o] = f[(b,n)][:1024] . W_lin[o][:1024] + b_lin[o]
// M=16384, N=768, K=1024. Block tile 128x128, BK=32, 8 warps (4x2),
// warp tile 32x64. 3-stage cp.async pipeline, one barrier per tile, issue
// hoisted ahead of the MMA phase. Both operands k-pair-permuted -> LDS.64
// fragment loads. EPILOGUE: stage the 128x128 tile in smem (bias added),
// then write the tap-split permuted layout g_weight[b][kk][n][mp] with
// consecutive threads sweeping consecutive mc — the 8-group permutation
// stays inside one 32B sector, so writes are sector-coalesced (fixes the
// 8x write amplification of the naive scatter).
// ---------------------------------------------------------------------------
#define G1_TILE   (128 * 36)
#define G1_SMEM   (6 * G1_TILE * 4)         // 110592 B  (>= 128*133*4 = 68096)

__global__ __launch_bounds__(256, 2)
void gemm1_kernel(const float* __restrict__ bl) {
    extern __shared__ uint32_t sm1[];
    uint32_t* Asb = sm1;                     // [3][G1_TILE]
    uint32_t* Bsb = sm1 + 3 * G1_TILE;       // [3][G1_TILE]
    const uint32_t s_as = (uint32_t)__cvta_generic_to_shared(Asb);
    const uint32_t s_bs = (uint32_t)__cvta_generic_to_shared(Bsb);

    const int tid  = threadIdx.x;
    const int m0   = blockIdx.y * 128;
    const int n0   = blockIdx.x * 128;
    const int warp = tid >> 5, lane = tid & 31;
    const int wm   = (warp >> 1) * 32;
    const int wn   = (warp & 1) * 64;
    const int gid  = lane >> 2, tig = lane & 3;
    const int lr   = tid >> 3;               // 0..31
    const int lc   = (tid & 7) * 4;          // 0..28

    float acc[2][8][4];
#pragma unroll
    for (int i = 0; i < 2; i++)
#pragma unroll
        for (int j = 0; j < 8; j++)
#pragma unroll
            for (int l = 0; l < 4; l++) acc[i][j][l] = 0.f;

    auto issue = [&](int t, int s) {
        const int kof = t * 32 + lc;
        const uint32_t da = s_as + (uint32_t)(s * G1_TILE + lr * 36 + lc) * 4;
        const uint32_t db = s_bs + (uint32_t)(s * G1_TILE + lr * 36 + lc) * 4;
#pragma unroll
        for (int it = 0; it < 4; it++) {
            int r = it * 32;
            cpa16(da + (uint32_t)(r * 36) * 4,
                  g_f  + (size_t)(m0 + lr + r) * H_ + kof);
            cpa16(db + (uint32_t)(r * 36) * 4,
                  g_wl + (size_t)(n0 + lr + r) * H_ + kof);
        }
    };

    const int T = H_ / 32;                   // 32 tiles
    issue(0, 0); CP_COMMIT();
    issue(1, 1); CP_COMMIT();

#pragma unroll 1
    for (int t = 0; t < T; t++) {
        CP_WAIT1();                          // tile t's group retired
        __syncthreads();                     // stage (t+2)%3 readers done
        if (t + 2 < T) issue(t + 2, (t + 2) % 3);
        CP_COMMIT();                         // uniform group accounting
        const int s = t % 3;
        const uint32_t* Af = Asb + s * G1_TILE;
        const uint32_t* Bf = Bsb + s * G1_TILE;
#pragma unroll
        for (int ks = 0; ks < 4; ks++) {
            const int kc = ks * 8 + tig * 2; // permuted pair position
            uint32_t af[2][4], bf[8][2];
#pragma unroll
            for (int mi = 0; mi < 2; mi++) {
                int row = wm + mi * 16 + gid;
                uint2 u0 = *(const uint2*)&Af[row * 36 + kc];
                uint2 u1 = *(const uint2*)&Af[(row + 8) * 36 + kc];
                af[mi][0] = u0.x; af[mi][2] = u0.y;   // k=tig, k=tig+4
                af[mi][1] = u1.x; af[mi][3] = u1.y;
            }
#pragma unroll
            for (int nt = 0; nt < 8; nt++) {
                int nr = wn + nt * 8 + gid;
                uint2 u = *(const uint2*)&Bf[nr * 36 + kc];
                bf[nt][0] = u.x; bf[nt][1] = u.y;
            }
#pragma unroll
            for (int mi = 0; mi < 2; mi++)
#pragma unroll
                for (int nt = 0; nt < 8; nt++)
                    mma8(acc[mi][nt], af[mi], bf[nt]);
        }
    }

    // ---- Epilogue phase 1: stage tile (bias added) into smem [c][133].
    CP_WAIT0();                              // no smem writes in flight
    __syncthreads();                         // all readers of pipeline smem done
    float* smf = (float*)sm1;
#pragma unroll
    for (int mi = 0; mi < 2; mi++) {
        int nloc = wm + mi * 16 + gid;
#pragma unroll
        for (int nt = 0; nt < 8; nt++) {
            int cl = wn + nt * 8 + tig * 2;
#pragma unroll
            for (int e = 0; e < 2; e++) {
                float bb = bl[n0 + cl + e];
                smf[(cl + e) * 133 + nloc]     = acc[mi][nt][e]     + bb;
                smf[(cl + e) * 133 + nloc + 8] = acc[mi][nt][e + 2] + bb;
            }
        }
    }
    __syncthreads();

    // ---- Epilogue phase 2: sector-coalesced permuted write.
    // Enumerate (kk, n, i) with i (plane-column index) fastest; consecutive
    // threads hit consecutive mc -> whole 32B sectors (perm is sector-local).
    const int bb_ = m0 >> 8;                 // batch (constant per CTA)
    const int nb  = m0 & 255;                // n base within batch
    int fc[3], cnt[3], off[4];
    off[0] = 0;
#pragma unroll
    for (int kk = 0; kk < 3; kk++) {
        int f0 = kk - (n0 % 3); f0 = (f0 % 3 + 3) % 3;
        fc[kk]  = f0;
        cnt[kk] = (128 - f0 + 2) / 3;
        off[kk + 1] = off[kk] + cnt[kk] * 128;
    }
    for (int idx = tid; idx < 128 * 128; idx += 256) {
        int kk  = (idx >= off[1]) + (idx >= off[2]);
        int rem = idx - off[kk];
        int n   = rem / cnt[kk];
        int i   = rem - n * cnt[kk];
        int c   = fc[kk] + 3 * i;
        int mc  = (n0 + c) / 3;
        int j   = mc & 7;
        int mp  = (mc & ~7) | ((j < 4) ? (j * 2) : ((j - 4) * 2 + 1));
        g_weight[(((size_t)bb_ * 3 + kk) * N_ + nb + n) * N_ + mp] =
            f2tf(smf[c * 133 + n]);
    }
}

// ---------------------------------------------------------------------------
// GEMM2 (dynamic conv as 3 shifted GEMMs):
//   out[b,n,h] = sum_{kk} sum_m W[b][kk][n][m] * k[b,m,h+kk-1]
// Flat iter t = mt*3 + kk. A tile (plane kk, PERMUTED m-cols mt*32..+31):
// 16B cp.async, 3 stages, LDS.64 fragment loads. B tile: k[b, mt*32..+31,
// h0-4..h0+131], 34 aligned 16B chunks/row, loaded once per mt, reused by
// all 3 taps (shift = smem col offset kk+3); 2 buffers; edge chunks
// zero-filled. B fragment bank pattern 8*tig+gid covers all 32 banks:
// conflict-free. Issue+commit precede the MMA phase.
// ---------------------------------------------------------------------------
#define G2_ATILE  (128 * 36)
#define G2_BTILE  (32 * 136)
#define G2_SMEM   ((3 * G2_ATILE + 2 * G2_BTILE) * 4)   // 90112 B

__global__ __launch_bounds__(256, 2)
void gemm2_kernel(float* __restrict__ Out) {
    extern __shared__ uint32_t sm2[];
    uint32_t* Asb = sm2;                         // [3][G2_ATILE]
    uint32_t* Bsb = sm2 + 3 * G2_ATILE;          // [2][G2_BTILE]
    const uint32_t s_as = (uint32_t)__cvta_generic_to_shared(Asb);
    const uint32_t s_bs = (uint32_t)__cvta_generic_to_shared(Bsb);

    const int tid = threadIdx.x;
    const int b   = blockIdx.z;
    const int m0  = blockIdx.y * 128;            // n dim: 0 or 128
    const int h0  = blockIdx.x * 128;            // 0..896
    const uint32_t* Wt = g_weight + (size_t)b * 3 * N_ * N_;
    const uint32_t* kb = g_k + (size_t)b * N_ * H_;

    const int warp = tid >> 5, lane = tid & 31;
    const int wm  = (warp >> 1) * 32;
    const int wn  = (warp & 1) * 64;
    const int gid = lane >> 2, tig = lane & 3;
    const int lr  = tid >> 3;
    const int lc  = (tid & 7) * 4;

    float acc[2][8][4];
#pragma unroll
    for (int i = 0; i < 2; i++)
#pragma unroll
        for (int j = 0; j < 8; j++)
#pragma unroll
            for (int l = 0; l < 4; l++) acc[i][j][l] = 0.f;

    auto issueA = [&](int t, int s) {
        const int kk = t % 3, mt = t / 3;
        const int cof = mt * 32 + lc;            // permuted groups stay intact
        const uint32_t da = s_as + (uint32_t)(s * G2_ATILE + lr * 36 + lc) * 4;
        const uint32_t* Ap = Wt + (size_t)kk * N_ * N_;
#pragma unroll
        for (int it = 0; it < 4; it++) {
            int r = it * 32;
            cpa16(da + (uint32_t)(r * 36) * 4,
                  Ap + (size_t)(m0 + lr + r) * N_ + cof);
        }
    };

    auto issueB = [&](int mt, int s) {
        const uint32_t db = s_bs + (uint32_t)(s * G2_BTILE) * 4;
        const int hbase = h0 - 4;                // 16B-aligned
#pragma unroll
        for (int i = 0; i < 5; i++) {
            int idx = tid + i * 256;             // 0..1087 (32*34)
            if (idx < 32 * 34) {
                int row = idx / 34, ch = idx - row * 34;
                int hs  = hbase + ch * 4;
                bool in = (hs >= 0) && (hs + 3 < H_);
                const uint32_t* src = in ? (kb + (size_t)(mt * 32 + row) * H_ + hs)
                                         : kb;   // clamped valid address
                cpa16z(db + (uint32_t)(row * 136 + ch * 4) * 4, src, in ? 16 : 0);
            }
        }
    };

    const int T = 24;                            // 8 m-tiles x 3 taps
    issueB(0, 0); issueA(0, 0); CP_COMMIT();
    issueA(1, 1); CP_COMMIT();

#pragma unroll 1
    for (int t = 0; t < T; t++) {
        CP_WAIT1();
        __syncthreads();
        const int kk = t % 3, mt = t / 3;
        if (t + 2 < T) issueA(t + 2, (t + 2) % 3);
        if (kk == 0 && mt + 1 < 8) issueB(mt + 1, (mt + 1) & 1);
        CP_COMMIT();
        const uint32_t* Ab = Asb + (t % 3) * G2_ATILE;
        const uint32_t* Bf = Bsb + (mt & 1) * G2_BTILE;
        const int csh = kk + 3;                  // smem col shift for this tap
#pragma unroll
        for (int ks = 0; ks < 4; ks++) {
            const int kc = ks * 8 + tig * 2;     // permuted m-pair position
            uint32_t af[2][4], bf[8][2];
#pragma unroll
            for (int mi = 0; mi < 2; mi++) {
                int row = wm + mi * 16 + gid;
                uint2 u0 = *(const uint2*)&Ab[row * 36 + kc];
                uint2 u1 = *(const uint2*)&Ab[(row + 8) * 36 + kc];
                af[mi][0] = u0.x; af[mi][2] = u0.y;
                af[mi][1] = u1.x; af[mi][3] = u1.y;
            }
#pragma unroll
            for (int nt = 0; nt < 8; nt++) {
                int pos = wn + nt * 8 + gid + csh;
                bf[nt][0] = Bf[(ks * 8 + tig) * 136 + pos];
                bf[nt][1] = Bf[(ks * 8 + tig + 4) * 136 + pos];
            }
#pragma unroll
            for (int mi = 0; mi < 2; mi++)
#pragma unroll
                for (int nt = 0; nt < 8; nt++)
                    mma8(acc[mi][nt], af[mi], bf[nt]);
        }
    }

#pragma unroll
    for (int mi = 0; mi < 2; mi++) {
        int r = m0 + wm + mi * 16 + gid;
        size_t rb = ((size_t)b * N_ + r) * H_;
#pragma unroll
        for (int nt = 0; nt < 8; nt++) {
            int c = h0 + wn + nt * 8 + tig * 2;
            *(float2*)(Out + rb + c) = make_float2(acc[mi][nt][0], acc[mi][nt][1]);
            *(float2*)(Out + rb + 8 * (size_t)H_ + c) =
                make_float2(acc[mi][nt][2], acc[mi][nt][3]);
        }
    }
}

// ---------------------------------------------------------------------------
// LayerNorm over H (in-place on d_out). One block per (b,n) row.
// ---------------------------------------------------------------------------
__global__ __launch_bounds__(256)
void ln_kernel(float* __restrict__ Out, const float* __restrict__ gamma,
               const float* __restrict__ beta) {
    __shared__ float red[8][2];
    const size_t row = blockIdx.x;
    float4* xp = (float4*)(Out + row * H_);
    float4 v = xp[threadIdx.x];
    float s = v.x + v.y + v.z + v.w;
    float q = v.x * v.x + v.y * v.y + v.z * v.z + v.w * v.w;
#pragma unroll
    for (int o = 16; o; o >>= 1) {
        s += __shfl_xor_sync(0xffffffffu, s, o);
        q += __shfl_xor_sync(0xffffffffu, q, o);
    }
    int warp = threadIdx.x >> 5, lane = threadIdx.x & 31;
    if (lane == 0) { red[warp][0] = s; red[warp][1] = q; }
    __syncthreads();
    s = 0.f; q = 0.f;
#pragma unroll
    for (int i = 0; i < 8; i++) { s += red[i][0]; q += red[i][1]; }
    float mu  = s * (1.f / H_);
    float var = q * (1.f / H_) - mu * mu;
    float inv = rsqrtf(var + 1e-5f);
    float4 g = ((const float4*)gamma)[threadIdx.x];
    float4 t = ((const float4*)beta)[threadIdx.x];
    v.x = (v.x - mu) * inv * g.x + t.x;
    v.y = (v.y - mu) * inv * g.y + t.y;
    v.z = (v.z - mu) * inv * g.z + t.z;
    v.w = (v.w - mu) * inv * g.w + t.w;
    xp[threadIdx.x] = v;
}

extern "C" void kernel_launch(void* const* d_in, const int* in_sizes, int n_in,
                              void* d_out, int out_size) {
    const float* f     = (const float*)d_in[0];
    const float* k     = (const float*)d_in[1];
    const float* Wl    = (const float*)d_in[2];
    const float* bl    = (const float*)d_in[3];
    const float* gamma = (const float*)d_in[4];
    const float* beta  = (const float*)d_in[5];
    float* out = (float*)d_out;

    cudaFuncSetAttribute(gemm1_kernel,
                         cudaFuncAttributeMaxDynamicSharedMemorySize, G1_SMEM);
    cudaFuncSetAttribute(gemm2_kernel,
                         cudaFuncAttributeMaxDynamicSharedMemorySize, G2_SMEM);

    uint32_t *d_gf, *d_gk, *d_gwl;
    cudaGetSymbolAddress((void**)&d_gf,  g_f);
    cudaGetSymbolAddress((void**)&d_gk,  g_k);
    cudaGetSymbolAddress((void**)&d_gwl, g_wl);

    cvt_perm_kernel<<<4096, 256>>>(f,  d_gf,  (B_ * N_ * H_) / 8);
    cvt_kernel     <<<4096, 256>>>(k,  d_gk,  (B_ * N_ * H_) / 4);
    cvt_perm_kernel<<<1024, 256>>>(Wl, d_gwl, (NK_ * H_) / 8);

    gemm1_kernel<<<dim3(6, 128), 256, G1_SMEM>>>(bl);
    gemm2_kernel<<<dim3(8, 2, 64), 256, G2_SMEM>>>(out);
    ln_kernel<<<B_ * N_, 256>>>(out, gamma, beta);
}

// round 14
// speedup vs baseline: 1.0186x; 1.0186x over previous
#include <cuda_runtime.h>
#include <cstdint>

#define B_  64
#define N_  256
#define H_  1024
#define NK_ 768     // N*K, K=3

// Device-global scratch (sanctioned no-allocation workaround).
// g_wraw:   gemm1 output, RAW layout [b*N+n][o], tf32 bits (bias added).
// g_weight: tap-split permuted [b][kk][n][m-PERMUTED], produced by repack.
// g_f/g_wl: k-dim pair-permuted within aligned 8-groups (0,4,1,5,2,6,3,7)
//           so MMA fragment pairs (k=tig, k=tig+4) are word-adjacent -> LDS.64.
// All tf32 bit patterns (cvt.rna once; identical numerics to per-read cvt).
__device__ uint32_t g_wraw  [(size_t)B_ * N_ * NK_];      // 48 MB
__device__ uint32_t g_weight[(size_t)B_ * 3 * N_ * N_];   // 48 MB
__device__ uint32_t g_f [(size_t)B_ * N_ * H_];           // f, k-perm
__device__ uint32_t g_k [(size_t)B_ * N_ * H_];           // k, UNpermuted
__device__ uint32_t g_wl[(size_t)NK_ * H_];               // W_lin, k-perm

__device__ __forceinline__ uint32_t f2tf(float x) {
    uint32_t r;
    asm("cvt.rna.tf32.f32 %0, %1;" : "=r"(r) : "f"(x));
    return r;
}

__device__ __forceinline__ void mma8(float* c, const uint32_t* a, const uint32_t* b) {
    asm volatile(
        "mma.sync.aligned.m16n8k8.row.col.f32.tf32.tf32.f32 "
        "{%0,%1,%2,%3}, {%4,%5,%6,%7}, {%8,%9}, {%0,%1,%2,%3};\n"
        : "+f"(c[0]), "+f"(c[1]), "+f"(c[2]), "+f"(c[3])
        : "r"(a[0]), "r"(a[1]), "r"(a[2]), "r"(a[3]), "r"(b[0]), "r"(b[1]));
}

__device__ __forceinline__ void cpa16(uint32_t dst, const void* src) {
    asm volatile("cp.async.cg.shared.global [%0], [%1], 16;\n"
                 :: "r"(dst), "l"(src) : "memory");
}
__device__ __forceinline__ void cpa16z(uint32_t dst, const void* src, int srcsz) {
    asm volatile("cp.async.cg.shared.global [%0], [%1], 16, %2;\n"
                 :: "r"(dst), "l"(src), "r"(srcsz) : "memory");
}
#define CP_COMMIT() asm volatile("cp.async.commit_group;\n" ::: "memory")
#define CP_WAIT1()  asm volatile("cp.async.wait_group 1;\n" ::: "memory")

// ---------------------------------------------------------------------------
// Pre-pass A: fp32 -> tf32 bits, k-PAIR-PERMUTED within each aligned 8-group.
// ---------------------------------------------------------------------------
__global__ void cvt_perm_kernel(const float* __restrict__ src,
                                uint32_t* __restrict__ dst, int n8) {
    int i = blockIdx.x * blockDim.x + threadIdx.x;
    int stride = gridDim.x * blockDim.x;
    for (; i < n8; i += stride) {
        float4 a = ((const float4*)src)[2 * i];
        float4 b = ((const float4*)src)[2 * i + 1];
        uint4 o0, o1;
        o0.x = f2tf(a.x); o0.y = f2tf(b.x); o0.z = f2tf(a.y); o0.w = f2tf(b.y);
        o1.x = f2tf(a.z); o1.y = f2tf(b.z); o1.z = f2tf(a.w); o1.w = f2tf(b.w);
        ((uint4*)dst)[2 * i]     = o0;
        ((uint4*)dst)[2 * i + 1] = o1;
    }
}

// Pre-pass B: plain fp32 -> tf32 bits (g_k; gemm2's B is not permuted).
__global__ void cvt_kernel(const float* __restrict__ src,
                           uint32_t* __restrict__ dst, int n4) {
    int i = blockIdx.x * blockDim.x + threadIdx.x;
    int stride = gridDim.x * blockDim.x;
    for (; i < n4; i += stride) {
        float4 v = ((const float4*)src)[i];
        uint4 o;
        o.x = f2tf(v.x); o.y = f2tf(v.y); o.z = f2tf(v.z); o.w = f2tf(v.w);
        ((uint4*)dst)[i] = o;
    }
}

// ---------------------------------------------------------------------------
// Repack: g_wraw[r][o] -> g_weight[b][kk][n][m-permuted].
// One thread per (row r, 24-word chunk g): reads 24 contiguous words
// (6x LDG.128, fully coalesced), emits one permuted 8-word group per tap
// plane (2x STG.128 each, coalesced across threads). No divisions.
// Perm: out position p(j) = (j<4) ? 2j : 2(j-4)+1 for source m index j.
// ---------------------------------------------------------------------------
__global__ __launch_bounds__(256)
void repack_kernel() {
    int tg = blockIdx.x * 256 + threadIdx.x;       // 0 .. 16384*32-1
    int r  = tg >> 5;                              // row  (b*256+n)
    int g  = tg & 31;                              // chunk: m-group of 8
    const uint32_t* src = g_wraw + (size_t)r * NK_ + g * 24;
    uint32_t v[24];
#pragma unroll
    for (int i = 0; i < 6; i++)
        *(uint4*)&v[i * 4] = ((const uint4*)src)[i];
    int b = r >> 8, n = r & 255;
#pragma unroll
    for (int kk = 0; kk < 3; kk++) {
        uint32_t o[8];
#pragma unroll
        for (int j = 0; j < 8; j++) {
            int p = (j < 4) ? (j * 2) : ((j - 4) * 2 + 1);
            o[p] = v[j * 3 + kk];
        }
        uint32_t* dst = g_weight + (((size_t)b * 3 + kk) * N_ + n) * N_ + g * 8;
        *(uint4*)&dst[0] = *(uint4*)&o[0];
        *(uint4*)&dst[4] = *(uint4*)&o[4];
    }
}

// ---------------------------------------------------------------------------
// GEMM1: weight[(b,n)][o] = f[(b,n)][:1024] . W_lin[o][:1024] + b_lin[o]
// M=16384, N=768, K=1024. Block tile 128x128, BK=32, 8 warps (4x2),
// warp tile 32x64. 3-stage cp.async pipeline, one barrier per tile, issue
// hoisted ahead of the MMA phase. Operands k-pair-permuted -> LDS.64
// fragment loads. EPILOGUE: plain contiguous float2 stores to g_wraw
// (the measured-fast R7 form); layout transform moved to repack_kernel.
// ---------------------------------------------------------------------------
#define G1_TILE   (128 * 36)
#define G1_SMEM   (6 * G1_TILE * 4)         // 110592 B

__global__ __launch_bounds__(256, 2)
void gemm1_kernel(const float* __restrict__ bl) {
    extern __shared__ uint32_t sm1[];
    uint32_t* Asb = sm1;                     // [3][G1_TILE]
    uint32_t* Bsb = sm1 + 3 * G1_TILE;       // [3][G1_TILE]
    const uint32_t s_as = (uint32_t)__cvta_generic_to_shared(Asb);
    const uint32_t s_bs = (uint32_t)__cvta_generic_to_shared(Bsb);

    const int tid  = threadIdx.x;
    const int m0   = blockIdx.y * 128;
    const int n0   = blockIdx.x * 128;
    const int warp = tid >> 5, lane = tid & 31;
    const int wm   = (warp >> 1) * 32;
    const int wn   = (warp & 1) * 64;
    const int gid  = lane >> 2, tig = lane & 3;
    const int lr   = tid >> 3;               // 0..31
    const int lc   = (tid & 7) * 4;          // 0..28

    float acc[2][8][4];
#pragma unroll
    for (int i = 0; i < 2; i++)
#pragma unroll
        for (int j = 0; j < 8; j++)
#pragma unroll
            for (int l = 0; l < 4; l++) acc[i][j][l] = 0.f;

    auto issue = [&](int t, int s) {
        const int kof = t * 32 + lc;
        const uint32_t da = s_as + (uint32_t)(s * G1_TILE + lr * 36 + lc) * 4;
        const uint32_t db = s_bs + (uint32_t)(s * G1_TILE + lr * 36 + lc) * 4;
#pragma unroll
        for (int it = 0; it < 4; it++) {
            int r = it * 32;
            cpa16(da + (uint32_t)(r * 36) * 4,
                  g_f  + (size_t)(m0 + lr + r) * H_ + kof);
            cpa16(db + (uint32_t)(r * 36) * 4,
                  g_wl + (size_t)(n0 + lr + r) * H_ + kof);
        }
    };

    const int T = H_ / 32;                   // 32 tiles
    issue(0, 0); CP_COMMIT();
    issue(1, 1); CP_COMMIT();

#pragma unroll 1
    for (int t = 0; t < T; t++) {
        CP_WAIT1();                          // tile t's group retired
        __syncthreads();                     // stage (t+2)%3 readers done
        if (t + 2 < T) issue(t + 2, (t + 2) % 3);
        CP_COMMIT();                         // uniform group accounting
        const int s = t % 3;
        const uint32_t* Af = Asb + s * G1_TILE;
        const uint32_t* Bf = Bsb + s * G1_TILE;
#pragma unroll
        for (int ks = 0; ks < 4; ks++) {
            const int kc = ks * 8 + tig * 2; // permuted pair position
            uint32_t af[2][4], bf[8][2];
#pragma unroll
            for (int mi = 0; mi < 2; mi++) {
                int row = wm + mi * 16 + gid;
                uint2 u0 = *(const uint2*)&Af[row * 36 + kc];
                uint2 u1 = *(const uint2*)&Af[(row + 8) * 36 + kc];
                af[mi][0] = u0.x; af[mi][2] = u0.y;   // k=tig, k=tig+4
                af[mi][1] = u1.x; af[mi][3] = u1.y;
            }
#pragma unroll
            for (int nt = 0; nt < 8; nt++) {
                int nr = wn + nt * 8 + gid;
                uint2 u = *(const uint2*)&Bf[nr * 36 + kc];
                bf[nt][0] = u.x; bf[nt][1] = u.y;
            }
#pragma unroll
            for (int mi = 0; mi < 2; mi++)
#pragma unroll
                for (int nt = 0; nt < 8; nt++)
                    mma8(acc[mi][nt], af[mi], bf[nt]);
        }
    }

    // Epilogue (R7 form): contiguous coalesced float2/uint2 stores.
#pragma unroll
    for (int mi = 0; mi < 2; mi++) {
        int r = m0 + wm + mi * 16 + gid;
#pragma unroll
        for (int nt = 0; nt < 8; nt++) {
            int c = n0 + wn + nt * 8 + tig * 2;
            float2 bb = *(const float2*)(bl + c);
            uint2 w0, w1;
            w0.x = f2tf(acc[mi][nt][0] + bb.x);
            w0.y = f2tf(acc[mi][nt][1] + bb.y);
            w1.x = f2tf(acc[mi][nt][2] + bb.x);
            w1.y = f2tf(acc[mi][nt][3] + bb.y);
            *(uint2*)(g_wraw + (size_t)r * NK_ + c) = w0;
            *(uint2*)(g_wraw + (size_t)(r + 8) * NK_ + c) = w1;
        }
    }
}

// ---------------------------------------------------------------------------
// GEMM2 (dynamic conv as 3 shifted GEMMs):
//   out[b,n,h] = sum_{kk} sum_m W[b][kk][n][m] * k[b,m,h+kk-1]
// Flat iter t = mt*3 + kk. A tile (plane kk, PERMUTED m-cols mt*32..+31):
// 16B cp.async, 3 stages, LDS.64 fragment loads. B tile: k[b, mt*32..+31,
// h0-4..h0+131], 34 aligned 16B chunks/row, loaded once per mt, reused by
// all 3 taps (shift = smem col offset kk+3); 2 buffers; edge chunks
// zero-filled. Issue+commit precede the MMA phase.
// ---------------------------------------------------------------------------
#define G2_ATILE  (128 * 36)
#define G2_BTILE  (32 * 136)
#define G2_SMEM   ((3 * G2_ATILE + 2 * G2_BTILE) * 4)   // 90112 B

__global__ __launch_bounds__(256, 2)
void gemm2_kernel(float* __restrict__ Out) {
    extern __shared__ uint32_t sm2[];
    uint32_t* Asb = sm2;                         // [3][G2_ATILE]
    uint32_t* Bsb = sm2 + 3 * G2_ATILE;          // [2][G2_BTILE]
    const uint32_t s_as = (uint32_t)__cvta_generic_to_shared(Asb);
    const uint32_t s_bs = (uint32_t)__cvta_generic_to_shared(Bsb);

    const int tid = threadIdx.x;
    const int b   = blockIdx.z;
    const int m0  = blockIdx.y * 128;            // n dim: 0 or 128
    const int h0  = blockIdx.x * 128;            // 0..896
    const uint32_t* Wt = g_weight + (size_t)b * 3 * N_ * N_;
    const uint32_t* kb = g_k + (size_t)b * N_ * H_;

    const int warp = tid >> 5, lane = tid & 31;
    const int wm  = (warp >> 1) * 32;
    const int wn  = (warp & 1) * 64;
    const int gid = lane >> 2, tig = lane & 3;
    const int lr  = tid >> 3;
    const int lc  = (tid & 7) * 4;

    float acc[2][8][4];
#pragma unroll
    for (int i = 0; i < 2; i++)
#pragma unroll
        for (int j = 0; j < 8; j++)
#pragma unroll
            for (int l = 0; l < 4; l++) acc[i][j][l] = 0.f;

    auto issueA = [&](int t, int s) {
        const int kk = t % 3, mt = t / 3;
        const int cof = mt * 32 + lc;            // permuted groups stay intact
        const uint32_t da = s_as + (uint32_t)(s * G2_ATILE + lr * 36 + lc) * 4;
        const uint32_t* Ap = Wt + (size_t)kk * N_ * N_;
#pragma unroll
        for (int it = 0; it < 4; it++) {
            int r = it * 32;
            cpa16(da + (uint32_t)(r * 36) * 4,
                  Ap + (size_t)(m0 + lr + r) * N_ + cof);
        }
    };

    auto issueB = [&](int mt, int s) {
        const uint32_t db = s_bs + (uint32_t)(s * G2_BTILE) * 4;
        const int hbase = h0 - 4;                // 16B-aligned
#pragma unroll
        for (int i = 0; i < 5; i++) {
            int idx = tid + i * 256;             // 0..1087 (32*34)
            if (idx < 32 * 34) {
                int row = idx / 34, ch = idx - row * 34;
                int hs  = hbase + ch * 4;
                bool in = (hs >= 0) && (hs + 3 < H_);
                const uint32_t* src = in ? (kb + (size_t)(mt * 32 + row) * H_ + hs)
                                         : kb;   // clamped valid address
                cpa16z(db + (uint32_t)(row * 136 + ch * 4) * 4, src, in ? 16 : 0);
            }
        }
    };

    const int T = 24;                            // 8 m-tiles x 3 taps
    issueB(0, 0); issueA(0, 0); CP_COMMIT();
    issueA(1, 1); CP_COMMIT();

#pragma unroll 1
    for (int t = 0; t < T; t++) {
        CP_WAIT1();
        __syncthreads();
        const int kk = t % 3, mt = t / 3;
        if (t + 2 < T) issueA(t + 2, (t + 2) % 3);
        if (kk == 0 && mt + 1 < 8) issueB(mt + 1, (mt + 1) & 1);
        CP_COMMIT();
        const uint32_t* Ab = Asb + (t % 3) * G2_ATILE;
        const uint32_t* Bf = Bsb + (mt & 1) * G2_BTILE;
        const int csh = kk + 3;                  // smem col shift for this tap
#pragma unroll
        for (int ks = 0; ks < 4; ks++) {
            const int kc = ks * 8 + tig * 2;     // permuted m-pair position
            uint32_t af[2][4], bf[8][2];
#pragma unroll
            for (int mi = 0; mi < 2; mi++) {
                int row = wm + mi * 16 + gid;
                uint2 u0 = *(const uint2*)&Ab[row * 36 + kc];
                uint2 u1 = *(const uint2*)&Ab[(row + 8) * 36 + kc];
                af[mi][0] = u0.x; af[mi][2] = u0.y;
                af[mi][1] = u1.x; af[mi][3] = u1.y;
            }
#pragma unroll
            for (int nt = 0; nt < 8; nt++) {
                int pos = wn + nt * 8 + gid + csh;
                bf[nt][0] = Bf[(ks * 8 + tig) * 136 + pos];
                bf[nt][1] = Bf[(ks * 8 + tig + 4) * 136 + pos];
            }
#pragma unroll
            for (int mi = 0; mi < 2; mi++)
#pragma unroll
                for (int nt = 0; nt < 8; nt++)
                    mma8(acc[mi][nt], af[mi], bf[nt]);
        }
    }

#pragma unroll
    for (int mi = 0; mi < 2; mi++) {
        int r = m0 + wm + mi * 16 + gid;
        size_t rb = ((size_t)b * N_ + r) * H_;
#pragma unroll
        for (int nt = 0; nt < 8; nt++) {
            int c = h0 + wn + nt * 8 + tig * 2;
            *(float2*)(Out + rb + c) = make_float2(acc[mi][nt][0], acc[mi][nt][1]);
            *(float2*)(Out + rb + 8 * (size_t)H_ + c) =
                make_float2(acc[mi][nt][2], acc[mi][nt][3]);
        }
    }
}

// ---------------------------------------------------------------------------
// LayerNorm over H (in-place on d_out). One block per (b,n) row.
// ---------------------------------------------------------------------------
__global__ __launch_bounds__(256)
void ln_kernel(float* __restrict__ Out, const float* __restrict__ gamma,
               const float* __restrict__ beta) {
    __shared__ float red[8][2];
    const size_t row = blockIdx.x;
    float4* xp = (float4*)(Out + row * H_);
    float4 v = xp[threadIdx.x];
    float s = v.x + v.y + v.z + v.w;
    float q = v.x * v.x + v.y * v.y + v.z * v.z + v.w * v.w;
#pragma unroll
    for (int o = 16; o; o >>= 1) {
        s += __shfl_xor_sync(0xffffffffu, s, o);
        q += __shfl_xor_sync(0xffffffffu, q, o);
    }
    int warp = threadIdx.x >> 5, lane = threadIdx.x & 31;
    if (lane == 0) { red[warp][0] = s; red[warp][1] = q; }
    __syncthreads();
    s = 0.f; q = 0.f;
#pragma unroll
    for (int i = 0; i < 8; i++) { s += red[i][0]; q += red[i][1]; }
    float mu  = s * (1.f / H_);
    float var = q * (1.f / H_) - mu * mu;
    float inv = rsqrtf(var + 1e-5f);
    float4 g = ((const float4*)gamma)[threadIdx.x];
    float4 t = ((const float4*)beta)[threadIdx.x];
    v.x = (v.x - mu) * inv * g.x + t.x;
    v.y = (v.y - mu) * inv * g.y + t.y;
    v.z = (v.z - mu) * inv * g.z + t.z;
    v.w = (v.w - mu) * inv * g.w + t.w;
    xp[threadIdx.x] = v;
}

extern "C" void kernel_launch(void* const* d_in, const int* in_sizes, int n_in,
                              void* d_out, int out_size) {
    const float* f     = (const float*)d_in[0];
    const float* k     = (const float*)d_in[1];
    const float* Wl    = (const float*)d_in[2];
    const float* bl    = (const float*)d_in[3];
    const float* gamma = (const float*)d_in[4];
    const float* beta  = (const float*)d_in[5];
    float* out = (float*)d_out;

    cudaFuncSetAttribute(gemm1_kernel,
                         cudaFuncAttributeMaxDynamicSharedMemorySize, G1_SMEM);
    cudaFuncSetAttribute(gemm2_kernel,
                         cudaFuncAttributeMaxDynamicSharedMemorySize, G2_SMEM);

    uint32_t *d_gf, *d_gk, *d_gwl;
    cudaGetSymbolAddress((void**)&d_gf,  g_f);
    cudaGetSymbolAddress((void**)&d_gk,  g_k);
    cudaGetSymbolAddress((void**)&d_gwl, g_wl);

    cvt_perm_kernel<<<4096, 256>>>(f,  d_gf,  (B_ * N_ * H_) / 8);
    cvt_kernel     <<<4096, 256>>>(k,  d_gk,  (B_ * N_ * H_) / 4);
    cvt_perm_kernel<<<1024, 256>>>(Wl, d_gwl, (NK_ * H_) / 8);

    gemm1_kernel<<<dim3(6, 128), 256, G1_SMEM>>>(bl);
    repack_kernel<<<(B_ * N_ * 32) / 256, 256>>>();
    gemm2_kernel<<<dim3(8, 2, 64), 256, G2_SMEM>>>(out);
    ln_kernel<<<B_ * N_, 256>>>(out, gamma, beta);
}